// round 16
// baseline (speedup 1.0000x reference)
#include <cuda_runtime.h>
#include <stdint.h>

// ---------------- problem constants ----------------
#define A_TOTAL   159882
#define BS        2
#define NLEV      5
#define NTASK     (BS*NLEV)
#define NPAD      1024
#define NW        32           // 1024 bits / 32
#define NB        65536        // histogram bins (top 16 bits of monotone key)
#define KSHIFT    16
#define TIECAP    4096
#define LCAP      (TIECAP + NPAD)   // max candidates in gather
#define PRE_TOPN  1000
#define POST_TOPN 1000

// level boundaries: 120000,30000,7500,1875,507
__device__ __forceinline__ int levelOf(int a){
    if (a < 120000) return 0;
    if (a < 150000) return 1;
    if (a < 157500) return 2;
    if (a < 159375) return 3;
    return 4;
}
__device__ __forceinline__ int levN(int l){
    const int n0 = 120000, n1 = 30000, n2 = 7500, n3 = 1875, n4 = 507;
    return l==0?n0 : l==1?n1 : l==2?n2 : l==3?n3 : n4;
}

// monotone key: larger float -> larger unsigned
__device__ __forceinline__ unsigned fkey(float f){
    unsigned u = __float_as_uint(f);
    return (u & 0x80000000u) ? ~u : (u | 0x80000000u);
}

// ---------------- scratch (device globals; loader-zeroed; self-cleaning per replay) ----------------
__device__ __align__(16) unsigned            g_hist[NTASK*NB];      // 2.62 MB
__device__ int                               g_tieCnt[NTASK];
__device__ int                               g_selCnt[NTASK];
__device__ int                               g_thrBin[NTASK];
__device__ int                               g_doneD[BS];
__device__ __align__(16) unsigned long long  g_tie[NTASK*TIECAP];
__device__ __align__(16) unsigned long long  g_sel[NTASK*NPAD];
__device__ __align__(16) float4              g_boxes[NTASK*NPAD];
__device__ float                             g_scores[NTASK*NPAD];
__device__ unsigned                          g_keys[NTASK*NPAD];
__device__ unsigned                          g_validMask[NTASK*NW];
__device__ __align__(16) unsigned            g_sup[NTASK*NPAD*NW];  // lower triangle written; upper stays 0
__device__ int                               g_kcnt[NTASK];
__device__ unsigned                          g_kkey[NTASK*NPAD];
__device__ int                               g_kref[NTASK*NPAD];

// ---------------- K1: per-task 65536-bin histogram (float4) ----------------
__global__ void k_hist(const float* __restrict__ obj){
    int q = blockIdx.x*blockDim.x + threadIdx.x;       // float4 index
    const int NQ = (BS*A_TOTAL)/4;                      // 79941 (exact)
    if (q >= NQ) return;
    float4 v = ((const float4*)obj)[q];
    int e0 = q*4;
    #pragma unroll
    for (int j=0;j<4;j++){
        int e = e0 + j;
        int b = (e >= A_TOTAL) ? 1 : 0;
        int a = e - b*A_TOTAL;
        int task = b*NLEV + levelOf(a);
        float f = j==0?v.x : j==1?v.y : j==2?v.z : v.w;
        atomicAdd(&g_hist[task*NB + (fkey(f) >> KSHIFT)], 1u);
    }
}

// ---------------- K2: zero counters + find threshold bin per task ----------------
__global__ void k_scan(){
    int task = blockIdx.x;
    int lev  = task % NLEV;
    int n = levN(lev);
    int k = n < PRE_TOPN ? n : PRE_TOPN;
    __shared__ unsigned ssum[1024];
    int t = threadIdx.x;
    if (t == 0){ g_selCnt[task] = 0; g_tieCnt[task] = 0; }   // consumed by prior replay's gather
    unsigned own = 0;
    const uint4* hb = (const uint4*)(g_hist + (size_t)task*NB + t*64);
    #pragma unroll
    for (int i=0;i<16;i++){ uint4 h = hb[i]; own += h.x+h.y+h.z+h.w; }
    ssum[t] = own;
    __syncthreads();
    for (int off=1; off<1024; off<<=1){
        unsigned v = (t+off<1024) ? ssum[t+off] : 0u;
        __syncthreads();
        ssum[t] += v;
        __syncthreads();
    }
    unsigned above = (t<1023) ? ssum[t+1] : 0u;
    if (k >= n){
        if (t==0) g_thrBin[task] = -1;    // select all
    } else if (above < (unsigned)k && above + own >= (unsigned)k){
        unsigned cum = above;
        for (int b2 = t*64+63; b2 >= t*64; --b2){
            cum += g_hist[(size_t)task*NB + b2];
            if (cum >= (unsigned)k){ g_thrBin[task] = b2; break; }
        }
    }
}

// ---------------- K3: compaction + histogram zeroing (wide grid) ----------------
__global__ void k_compact(const float* __restrict__ obj){
    int q = blockIdx.x*blockDim.x + threadIdx.x;
    const int NQ = (BS*A_TOTAL)/4;
    float4 v = make_float4(0.f,0.f,0.f,0.f);
    bool active = q < NQ;
    if (active) v = ((const float4*)obj)[q];
    int e0 = q*4;
    unsigned lanemask_lt = (1u << (threadIdx.x & 31)) - 1u;
    int taskA = -1, taskB = -1, thrA = 0x7FFFFFFF, thrB = 0x7FFFFFFF;
    if (active){
        int bA = (e0 >= A_TOTAL) ? 1 : 0;
        taskA = bA*NLEV + levelOf(e0 - bA*A_TOTAL);
        int e3 = e0 + 3;
        int bB = (e3 >= A_TOTAL) ? 1 : 0;
        taskB = bB*NLEV + levelOf(e3 - bB*A_TOTAL);
        thrA = g_thrBin[taskA];
        thrB = (taskB == taskA) ? thrA : g_thrBin[taskB];
    }
    #pragma unroll
    for (int j=0;j<4;j++){
        int e = e0 + j;
        int b = (e >= A_TOTAL) ? 1 : 0;
        int a = e - b*A_TOTAL;
        int task = b*NLEV + levelOf(a);
        float f = j==0?v.x : j==1?v.y : j==2?v.z : v.w;
        unsigned key = fkey(f);
        int bin = (int)(key >> KSHIFT);
        int thr = active ? ((task == taskA) ? thrA : thrB) : 0x7FFFFFFF;
        bool isSel = active && (bin > thr);
        bool isTie = active && (bin == thr);
        unsigned long long packed =
            ((unsigned long long)key << 32) | (unsigned long long)(0xFFFFFFFFu - (unsigned)a);
        int task0 = __shfl_sync(0xffffffffu, task, 0);
        bool sameTask = __all_sync(0xffffffffu, task == task0);
        if (sameTask){
            unsigned msel = __ballot_sync(0xffffffffu, isSel);
            unsigned mtie = __ballot_sync(0xffffffffu, isTie);
            int baseSel = 0, baseTie = 0;
            int leader = (threadIdx.x & 31) == 0;
            if (leader && msel) baseSel = atomicAdd(&g_selCnt[task0], __popc(msel));
            if (leader && mtie) baseTie = atomicAdd(&g_tieCnt[task0], __popc(mtie));
            baseSel = __shfl_sync(0xffffffffu, baseSel, 0);
            baseTie = __shfl_sync(0xffffffffu, baseTie, 0);
            if (isSel){
                int p = baseSel + __popc(msel & lanemask_lt);
                g_sel[task0*NPAD + p] = packed;
            } else if (isTie){
                int p = baseTie + __popc(mtie & lanemask_lt);
                if (p < TIECAP) g_tie[task0*TIECAP + p] = packed;
            }
        } else {
            if (isSel){
                int p = atomicAdd(&g_selCnt[task], 1);
                g_sel[task*NPAD + p] = packed;
            } else if (isTie){
                int p = atomicAdd(&g_tieCnt[task], 1);
                if (p < TIECAP) g_tie[task*TIECAP + p] = packed;
            }
        }
    }
    // zero the histogram for the next replay (scan already consumed it; wide grid)
    int gsize = gridDim.x * blockDim.x;
    int gid = blockIdx.x*blockDim.x + threadIdx.x;
    uint4 z = make_uint4(0,0,0,0);
    for (int i = gid; i < NTASK*NB/4; i += gsize) ((uint4*)g_hist)[i] = z;
}

// ---------------- K4: one-shot rank-by-count over all candidates, decode+clip ----------------
__global__ void k_gather(const float* __restrict__ pred, const float* __restrict__ obj,
                         const float* __restrict__ anch, const float* __restrict__ vsz){
    __shared__ unsigned long long sarr[LCAP];     // 40 KB candidates (sel ++ ties)
    __shared__ unsigned long long ss[NPAD];       //  8 KB ranked output
    int task = blockIdx.x;
    int img = task / NLEV, lev = task % NLEV;
    int n = levN(lev);
    int k = n < PRE_TOPN ? n : PRE_TOPN;
    int tid = threadIdx.x;
    int selCnt = g_selCnt[task];
    int tc = g_tieCnt[task]; if (tc > TIECAP) tc = TIECAP;
    int L = selCnt + tc;                          // <= LCAP
    // load candidates: sel first, then ties
    for (int i = tid; i < selCnt; i += 1024) sarr[i] = g_sel[task*NPAD + i];
    for (int i = tid; i < tc; i += 1024) sarr[selCnt + i] = g_tie[task*TIECAP + i];
    ss[tid] = 0ull;
    __syncthreads();
    // rank each candidate among all (unique keys -> unique ranks); broadcast reads
    for (int i = tid; i < L; i += 1024){
        unsigned long long mine = sarr[i];
        int rank = 0;
        int j = 0;
        for (; j + 8 <= L; j += 8){
            rank += (sarr[j+0] > mine);
            rank += (sarr[j+1] > mine);
            rank += (sarr[j+2] > mine);
            rank += (sarr[j+3] > mine);
            rank += (sarr[j+4] > mine);
            rank += (sarr[j+5] > mine);
            rank += (sarr[j+6] > mine);
            rank += (sarr[j+7] > mine);
        }
        for (; j < L; j++) rank += (sarr[j] > mine);
        if (rank < k) ss[rank] = mine;
    }
    __syncthreads();

    // decode rank tid
    unsigned long long v = ss[tid];
    int r = tid;
    float4 box = make_float4(0.f,0.f,0.f,0.f);
    float score = 0.f; unsigned key = 0u; bool valid = false;
    if (r < k){
        key = (unsigned)(v >> 32);
        unsigned a = 0xFFFFFFFFu - (unsigned)(v & 0xFFFFFFFFull);
        float4 pp = __ldg(((const float4*)pred) + ((size_t)img*A_TOTAL + a));
        float4 an = __ldg(((const float4*)anch) + a);
        float awx = an.z - an.x, awy = an.w - an.y;
        float cx = an.x + 0.5f*awx + pp.x*awx;
        float cy = an.y + 0.5f*awy + pp.y*awy;
        float wx = expf(pp.z)*awx;
        float wy = expf(pp.w)*awy;
        float x1 = cx - 0.5f*wx, y1 = cy - 0.5f*wy;
        float x2 = x1 + wx,      y2 = y1 + wy;
        float W = vsz[img*2+0], H = vsz[img*2+1];
        x1 = fminf(fmaxf(x1,0.f),W); x2 = fminf(fmaxf(x2,0.f),W);
        y1 = fminf(fmaxf(y1,0.f),H); y2 = fminf(fmaxf(y2,0.f),H);
        box = make_float4(x1,y1,x2,y2);
        valid = (x2 - x1 > 0.001f) && (y2 - y1 > 0.001f);
        score = obj[(size_t)img*A_TOTAL + a];
    }
    g_boxes [task*NPAD + r] = box;
    g_scores[task*NPAD + r] = score;
    g_keys  [task*NPAD + r] = key;
    unsigned vm = __ballot_sync(0xffffffffu, valid);
    if ((tid & 31) == 0) g_validMask[task*NW + (tid>>5)] = vm;
}

// ---------------- K5: suppression bit-matrix, lower triangle, 32 rows/block ----------------
__global__ void __launch_bounds__(1024) k_supmat(){
    int task = blockIdx.y, bx = blockIdx.x;       // bx in [0,32): rows bx*32..bx*32+31
    __shared__ float4 sbox[NPAD];   // 16 KB
    __shared__ float  sar [NPAD];   //  4 KB
    int tid = threadIdx.x;
    int nwords = bx + 1;                          // all rows in block share (row>>5)==bx
    int lim = nwords * 32;
    for (int j=tid; j<lim; j+=1024){
        float4 bb = g_boxes[task*NPAD + j];
        sbox[j] = bb;
        sar[j]  = (bb.z - bb.x) * (bb.w - bb.y);
    }
    __syncthreads();
    int wid = tid >> 5, lane = tid & 31;
    int i = bx*32 + wid;           // row
    float4 bi = sbox[i];
    float tden = sar[i] + 1e-9f;
    unsigned* dst = &g_sup[((size_t)task*NPAD + i)*NW];
    for (int jw=0; jw<nwords; jw++){
        int j = jw*32 + lane;
        float4 bj = sbox[j];
        float xx1 = fmaxf(bi.x, bj.x);
        float yy1 = fmaxf(bi.y, bj.y);
        float xx2 = fminf(bi.z, bj.z);
        float yy2 = fminf(bi.w, bj.w);
        float iw = fmaxf(xx2-xx1, 0.f);
        float ih = fmaxf(yy2-yy1, 0.f);
        float inter = iw*ih;
        float den = tden + sar[j] - inter;
        bool sup = inter > 0.7f*den;        // == (iou > 0.7)
        unsigned m = __ballot_sync(0xffffffffu, sup);
        if (lane == 0) dst[jw] = m;
    }
}

// ---------------- K6: fixed-point NMS + fallback + (last task per image) merge/output ----------------
__global__ void __launch_bounds__(1024) k_nms_out(float* __restrict__ out){
    int task = blockIdx.x;
    int img = task / NLEV;
    int tid = threadIdx.x;
    int myw = tid >> 5, lane = tid & 31;
    unsigned row[NW];
    const uint4* rp = (const uint4*)(g_sup + ((size_t)task*NPAD + tid)*NW);
    #pragma unroll
    for (int q=0;q<8;q++){
        uint4 v = rp[q];
        row[q*4+0]=v.x; row[q*4+1]=v.y; row[q*4+2]=v.z; row[q*4+3]=v.w;
    }
    #pragma unroll
    for (int w=0;w<NW;w++) if (w > myw) row[w] = 0u;
    row[myw] &= (lane ? ((1u<<lane)-1u) : 0u);
    bool valid = (g_validMask[task*NW + myw] >> lane) & 1u;

    __shared__ unsigned skeep[NW];
    __shared__ int schanged, sconv;
    if (tid < NW) skeep[tid] = g_validMask[task*NW + tid];
    if (tid == 0) sconv = 0;
    __syncthreads();

    for (int it=0; it<24; ++it){
        unsigned any = 0u;
        #pragma unroll
        for (int w=0;w<NW;w++) any |= row[w] & skeep[w];
        bool nk = valid && (any == 0u);
        unsigned bw = __ballot_sync(0xffffffffu, nk);
        if (tid == 0) schanged = 0;
        __syncthreads();
        if (lane == 0){
            if (bw != skeep[myw]) schanged = 1;
            skeep[myw] = bw;
        }
        __syncthreads();
        if (!schanged){ if (tid==0) sconv = 1; break; }
    }
    __syncthreads();

    if (!sconv){
        // sequential greedy fallback (warp 0), lower-triangle-correct
        if (tid < 32){
            unsigned validw = g_validMask[task*NW + lane];
            const unsigned* rowbase = g_sup + (size_t)task*NPAD*NW;
            unsigned keptw = 0u;
            auto loadw = [&](int nx)->unsigned{
                if (nx >= NPAD) return 0u;
                int wi = nx >> 5;
                if (lane > wi) return 0u;
                unsigned r = rowbase[(size_t)nx*NW + lane];
                if (lane == wi) r &= ((nx & 31) ? ((1u<<(nx&31))-1u) : 0u);
                return r;
            };
            unsigned ring[8];
            #pragma unroll
            for (int d=0; d<8; d++) ring[d] = loadw(d);
            for (int ib=0; ib<NPAD; ib+=8){
                #pragma unroll
                for (int u=0; u<8; u++){
                    int i = ib + u;
                    int wi = i >> 5;
                    bool hit = (ring[u] & keptw) != 0u;
                    unsigned anyhit = __ballot_sync(0xffffffffu, hit);
                    unsigned vv = __shfl_sync(0xffffffffu, validw, wi);
                    bool take = ((vv >> (i & 31)) & 1u) && (anyhit == 0u);
                    if (take && lane == wi) keptw |= (1u << (i & 31));
                    ring[u] = loadw(i + 8);
                }
            }
            skeep[lane] = keptw;
        }
        __syncthreads();
    }

    // compaction (warp 0): kept list in score-descending order
    if (tid < 32){
        unsigned keepw = skeep[lane];
        unsigned cnt = __popc(keepw);
        unsigned incl = cnt;
        #pragma unroll
        for (int d=1; d<32; d<<=1){
            unsigned v = __shfl_up_sync(0xffffffffu, incl, d);
            if (lane >= d) incl += v;
        }
        unsigned excl = incl - cnt;
        unsigned total = __shfl_sync(0xffffffffu, incl, 31);
        if (lane == 0) g_kcnt[task] = (int)total;
        unsigned m = keepw; int p = (int)excl;
        while (m){
            int b = __ffs((int)m) - 1; m &= m - 1;
            int r = lane*32 + b;
            g_kkey[task*NPAD + p] = g_keys[task*NPAD + r];
            g_kref[task*NPAD + p] = r;
            p++;
        }
    }
    __syncthreads();
    __shared__ int slastD;
    if (tid == 0){
        __threadfence();                                    // release my kkey/kref/kcnt
        slastD = (atomicAdd(&g_doneD[img], 1) == NLEV-1) ? 1 : 0;
    }
    __syncthreads();
    if (!slastD) return;
    if (tid == 0){ g_doneD[img] = 0; __threadfence(); }     // acquire peers' writes; reset for next replay
    __syncthreads();

    // ---- merge phase: 5-way co-ranking merge for this image ----
    __shared__ unsigned skey[NLEV*NPAD];  // 20 KB
    __shared__ int scnt[NLEV];
    if (tid < NLEV) scnt[tid] = g_kcnt[img*NLEV + tid];
    for (int lt=0; lt<NLEV; lt++)
        skey[lt*NPAD + tid] = g_kkey[(img*NLEV + lt)*NPAD + tid];
    for (int i=tid; i<POST_TOPN*4; i+=1024) out[img*POST_TOPN*4 + i] = 0.f;
    for (int i=tid; i<POST_TOPN;   i+=1024) out[BS*POST_TOPN*4 + img*POST_TOPN + i] = 0.f;
    __syncthreads();
    for (int e=tid; e<NLEV*NPAD; e+=1024){
        int lt = e >> 10, p = e & (NPAD-1);
        if (p < scnt[lt]){
            unsigned key = skey[lt*NPAD + p];
            int rank = p;
            #pragma unroll
            for (int o=0; o<NLEV; o++){
                if (o == lt) continue;
                int c = scnt[o];
                const unsigned* arr = skey + o*NPAD;
                int lo=0, hi=c;
                while (lo < hi){
                    int mid = (lo+hi) >> 1;
                    bool before = (o < lt) ? (arr[mid] >= key) : (arr[mid] > key);
                    if (before) lo = mid+1; else hi = mid;
                }
                rank += lo;
            }
            if (rank < POST_TOPN){
                int t2 = img*NLEV + lt;
                int r = g_kref[t2*NPAD + p];
                float4 bb = g_boxes[t2*NPAD + r];
                float sc  = g_scores[t2*NPAD + r];
                float* ob = out + (img*POST_TOPN + rank)*4;
                ob[0]=bb.x; ob[1]=bb.y; ob[2]=bb.z; ob[3]=bb.w;
                out[BS*POST_TOPN*4 + img*POST_TOPN + rank] = sc;
            }
        }
    }
}

// ---------------- launch ----------------
extern "C" void kernel_launch(void* const* d_in, const int* in_sizes, int n_in,
                              void* d_out, int out_size){
    const float* pred = (const float*)d_in[0];   // (2, A, 4)
    const float* obj  = (const float*)d_in[1];   // (2, A, 1)
    const float* anch = (const float*)d_in[2];   // (A, 4)
    const float* vsz  = (const float*)d_in[3];   // (2, 2)
    float* out = (float*)d_out;                  // [boxes(2,1000,4) | scores(2,1000)]

    const int NQ = (BS*A_TOTAL)/4;               // 79941 float4s
    k_hist   <<<(NQ + 255)/256, 256>>>(obj);
    k_scan   <<<NTASK, 1024>>>();
    k_compact<<<(NQ + 255)/256, 256>>>(obj);
    k_gather <<<NTASK, 1024>>>(pred, obj, anch, vsz);
    k_supmat <<<dim3(NPAD/32, NTASK), 1024>>>();
    k_nms_out<<<NTASK, 1024>>>(out);
}

// round 17
// speedup vs baseline: 1.2840x; 1.2840x over previous
#include <cuda_runtime.h>
#include <stdint.h>

// ---------------- problem constants ----------------
#define A_TOTAL   159882
#define BS        2
#define NLEV      5
#define NTASK     (BS*NLEV)
#define NPAD      1024
#define NW        32           // 1024 bits / 32
#define NB        65536        // histogram bins (top 16 bits of monotone key)
#define KSHIFT    16
#define TIECAP    4096
#define PRE_TOPN  1000
#define POST_TOPN 1000

// level boundaries: 120000,30000,7500,1875,507
__device__ __forceinline__ int levelOf(int a){
    if (a < 120000) return 0;
    if (a < 150000) return 1;
    if (a < 157500) return 2;
    if (a < 159375) return 3;
    return 4;
}
__device__ __forceinline__ int levN(int l){
    const int n0 = 120000, n1 = 30000, n2 = 7500, n3 = 1875, n4 = 507;
    return l==0?n0 : l==1?n1 : l==2?n2 : l==3?n3 : n4;
}

// monotone key: larger float -> larger unsigned
__device__ __forceinline__ unsigned fkey(float f){
    unsigned u = __float_as_uint(f);
    return (u & 0x80000000u) ? ~u : (u | 0x80000000u);
}

// ---------------- scratch (device globals; loader-zeroed; self-cleaning per replay) ----------------
__device__ __align__(16) unsigned            g_hist[NTASK*NB];      // 2.62 MB
__device__ int                               g_tieCnt[NTASK];
__device__ int                               g_selCnt[NTASK];
__device__ int                               g_thrBin[NTASK];
__device__ int                               g_doneD[BS];
__device__ __align__(16) unsigned long long  g_tie[NTASK*TIECAP];
__device__ __align__(16) unsigned long long  g_sel[NTASK*NPAD];
__device__ __align__(16) float4              g_boxes[NTASK*NPAD];
__device__ float                             g_scores[NTASK*NPAD];
__device__ unsigned                          g_keys[NTASK*NPAD];
__device__ unsigned                          g_validMask[NTASK*NW];
__device__ __align__(16) unsigned            g_sup[NTASK*NPAD*NW];  // lower triangle written; upper stays 0
__device__ int                               g_kcnt[NTASK];
__device__ unsigned                          g_kkey[NTASK*NPAD];
__device__ int                               g_kref[NTASK*NPAD];

// ---------------- K1: per-task 65536-bin histogram (float4) ----------------
__global__ void k_hist(const float* __restrict__ obj){
    int q = blockIdx.x*blockDim.x + threadIdx.x;       // float4 index
    const int NQ = (BS*A_TOTAL)/4;                      // 79941 (exact)
    if (q >= NQ) return;
    float4 v = ((const float4*)obj)[q];
    int e0 = q*4;
    #pragma unroll
    for (int j=0;j<4;j++){
        int e = e0 + j;
        int b = (e >= A_TOTAL) ? 1 : 0;
        int a = e - b*A_TOTAL;
        int task = b*NLEV + levelOf(a);
        float f = j==0?v.x : j==1?v.y : j==2?v.z : v.w;
        atomicAdd(&g_hist[task*NB + (fkey(f) >> KSHIFT)], 1u);
    }
}

// ---------------- K2: zero counters + threshold bin (warp-shuffle suffix scan) ----------------
__global__ void k_scan(){
    int task = blockIdx.x;
    int lev  = task % NLEV;
    int n = levN(lev);
    int k = n < PRE_TOPN ? n : PRE_TOPN;
    __shared__ unsigned swarp[32];
    int t = threadIdx.x;
    int lane = t & 31, wid = t >> 5;
    if (t == 0){ g_selCnt[task] = 0; g_tieCnt[task] = 0; }   // consumed by prior replay's gather
    unsigned own = 0;
    const uint4* hb = (const uint4*)(g_hist + (size_t)task*NB + t*64);
    #pragma unroll
    for (int i=0;i<16;i++){ uint4 h = hb[i]; own += h.x+h.y+h.z+h.w; }
    // intra-warp inclusive suffix sum (incl = sum of own over lanes >= lane)
    unsigned incl = own;
    #pragma unroll
    for (int d=1; d<32; d<<=1){
        unsigned x = __shfl_down_sync(0xffffffffu, incl, d);
        if (lane + d < 32) incl += x;
    }
    if (lane == 0) swarp[wid] = incl;     // warp total
    __syncthreads();
    if (t < 32){
        unsigned wv = swarp[t];
        unsigned winc = wv;
        #pragma unroll
        for (int d=1; d<32; d<<=1){
            unsigned x = __shfl_down_sync(0xffffffffu, winc, d);
            if (t + d < 32) winc += x;
        }
        swarp[t] = winc - wv;             // sum of warps strictly after t
    }
    __syncthreads();
    unsigned above = swarp[wid] + (incl - own);   // keys in bins strictly above my 64-bin range
    if (k >= n){
        if (t==0) g_thrBin[task] = -1;    // select all
    } else if (above < (unsigned)k && above + own >= (unsigned)k){
        unsigned cum = above;
        for (int b2 = t*64+63; b2 >= t*64; --b2){
            cum += g_hist[(size_t)task*NB + b2];
            if (cum >= (unsigned)k){ g_thrBin[task] = b2; break; }
        }
    }
}

// ---------------- K3: compaction + histogram zeroing (wide grid) ----------------
__global__ void k_compact(const float* __restrict__ obj){
    int q = blockIdx.x*blockDim.x + threadIdx.x;
    const int NQ = (BS*A_TOTAL)/4;
    float4 v = make_float4(0.f,0.f,0.f,0.f);
    bool active = q < NQ;
    if (active) v = ((const float4*)obj)[q];
    int e0 = q*4;
    unsigned lanemask_lt = (1u << (threadIdx.x & 31)) - 1u;
    int taskA = -1, taskB = -1, thrA = 0x7FFFFFFF, thrB = 0x7FFFFFFF;
    if (active){
        int bA = (e0 >= A_TOTAL) ? 1 : 0;
        taskA = bA*NLEV + levelOf(e0 - bA*A_TOTAL);
        int e3 = e0 + 3;
        int bB = (e3 >= A_TOTAL) ? 1 : 0;
        taskB = bB*NLEV + levelOf(e3 - bB*A_TOTAL);
        thrA = g_thrBin[taskA];
        thrB = (taskB == taskA) ? thrA : g_thrBin[taskB];
    }
    #pragma unroll
    for (int j=0;j<4;j++){
        int e = e0 + j;
        int b = (e >= A_TOTAL) ? 1 : 0;
        int a = e - b*A_TOTAL;
        int task = b*NLEV + levelOf(a);
        float f = j==0?v.x : j==1?v.y : j==2?v.z : v.w;
        unsigned key = fkey(f);
        int bin = (int)(key >> KSHIFT);
        int thr = active ? ((task == taskA) ? thrA : thrB) : 0x7FFFFFFF;
        bool isSel = active && (bin > thr);
        bool isTie = active && (bin == thr);
        unsigned long long packed =
            ((unsigned long long)key << 32) | (unsigned long long)(0xFFFFFFFFu - (unsigned)a);
        int task0 = __shfl_sync(0xffffffffu, task, 0);
        bool sameTask = __all_sync(0xffffffffu, task == task0);
        if (sameTask){
            unsigned msel = __ballot_sync(0xffffffffu, isSel);
            unsigned mtie = __ballot_sync(0xffffffffu, isTie);
            int baseSel = 0, baseTie = 0;
            int leader = (threadIdx.x & 31) == 0;
            if (leader && msel) baseSel = atomicAdd(&g_selCnt[task0], __popc(msel));
            if (leader && mtie) baseTie = atomicAdd(&g_tieCnt[task0], __popc(mtie));
            baseSel = __shfl_sync(0xffffffffu, baseSel, 0);
            baseTie = __shfl_sync(0xffffffffu, baseTie, 0);
            if (isSel){
                int p = baseSel + __popc(msel & lanemask_lt);
                g_sel[task0*NPAD + p] = packed;
            } else if (isTie){
                int p = baseTie + __popc(mtie & lanemask_lt);
                if (p < TIECAP) g_tie[task0*TIECAP + p] = packed;
            }
        } else {
            if (isSel){
                int p = atomicAdd(&g_selCnt[task], 1);
                g_sel[task*NPAD + p] = packed;
            } else if (isTie){
                int p = atomicAdd(&g_tieCnt[task], 1);
                if (p < TIECAP) g_tie[task*TIECAP + p] = packed;
            }
        }
    }
    // zero the histogram for the next replay (scan already consumed it; wide grid)
    int gsize = gridDim.x * blockDim.x;
    int gid = blockIdx.x*blockDim.x + threadIdx.x;
    uint4 z = make_uint4(0,0,0,0);
    for (int i = gid; i < NTASK*NB/4; i += gsize) ((uint4*)g_hist)[i] = z;
}

// ---------------- K4: resolve ties, 4x256-chunk bitonic + co-rank merge, decode+clip ----------------
__global__ void k_gather(const float* __restrict__ pred, const float* __restrict__ obj,
                         const float* __restrict__ anch, const float* __restrict__ vsz){
    __shared__ unsigned long long sbuf[2][NPAD];  // 16 KB (ping-pong / sorted chunks / ranked out)
    __shared__ unsigned long long sties[TIECAP];  // 32 KB
    int task = blockIdx.x;
    int img = task / NLEV, lev = task % NLEV;
    int n = levN(lev);
    int k = n < PRE_TOPN ? n : PRE_TOPN;
    int tid = threadIdx.x;
    int selCnt = g_selCnt[task];
    int tc = g_tieCnt[task]; if (tc > TIECAP) tc = TIECAP;
    int need = k - selCnt;
    for (int i = tid; i < tc; i += 1024) sties[i] = g_tie[task*TIECAP + i];
    sbuf[0][tid] = (tid < selCnt) ? g_sel[task*NPAD + tid] : 0ull;
    __syncthreads();
    if (need > 0){
        // rank-by-count over ties only (tc ~ tens at NB=65536); unique keys -> unique ranks
        for (int i = tid; i < tc; i += 1024){
            unsigned long long mine = sties[i];
            int rank = 0;
            for (int j=0;j<tc;j++) rank += (sties[j] > mine);
            if (rank < need) sbuf[0][selCnt + rank] = mine;
        }
        __syncthreads();
    }
    // sort 4 independent 256-chunks descending (hybrid bitonic, double-buffered)
    unsigned long long v = sbuf[0][tid];
    int p = tid & 255, chunk = tid >> 8;
    int pb = 0;
    for (int size=2; size<=256; size<<=1){
        bool dirDesc = (p & size) == 0;
        for (int stride=size>>1; stride>=32; stride>>=1){
            sbuf[pb][tid] = v;
            __syncthreads();
            unsigned long long o = sbuf[pb][tid ^ stride];   // stride<256 -> stays in chunk
            bool takeMax = (dirDesc == ((p & stride) == 0));
            v = takeMax ? (v > o ? v : o) : (v < o ? v : o);
            pb ^= 1;
        }
        int s0 = (size>>1) < 16 ? (size>>1) : 16;
        for (int stride=s0; stride>=1; stride>>=1){
            unsigned long long o = __shfl_xor_sync(0xffffffffu, v, stride);
            bool takeMax = (dirDesc == ((p & stride) == 0));
            v = takeMax ? (v > o ? v : o) : (v < o ? v : o);
        }
    }
    // publish sorted chunks; compute global rank by co-ranking the other 3 chunks
    sbuf[pb][tid] = v;
    __syncthreads();
    int rank = p;                       // strictly-greater count within own chunk (keys unique; zeros rank late)
    #pragma unroll
    for (int o=0; o<4; o++){
        if (o == chunk) continue;
        const unsigned long long* arr = &sbuf[pb][o << 8];
        int lo = 0, hi = 256;
        while (lo < hi){
            int mid = (lo + hi) >> 1;
            if (arr[mid] > v) lo = mid + 1; else hi = mid;
        }
        rank += lo;
    }
    unsigned long long* outb = &sbuf[pb ^ 1][0];
    outb[rank < NPAD ? rank : NPAD-1] = v;   // real keys: unique ranks 0..k-1; zero-pads land >=k (ignored)
    __syncthreads();
    v = outb[tid];
    // decode rank tid
    int r = tid;
    float4 box = make_float4(0.f,0.f,0.f,0.f);
    float score = 0.f; unsigned key = 0u; bool valid = false;
    if (r < k){
        key = (unsigned)(v >> 32);
        unsigned a = 0xFFFFFFFFu - (unsigned)(v & 0xFFFFFFFFull);
        float4 pp = __ldg(((const float4*)pred) + ((size_t)img*A_TOTAL + a));
        float4 an = __ldg(((const float4*)anch) + a);
        float awx = an.z - an.x, awy = an.w - an.y;
        float cx = an.x + 0.5f*awx + pp.x*awx;
        float cy = an.y + 0.5f*awy + pp.y*awy;
        float wx = expf(pp.z)*awx;
        float wy = expf(pp.w)*awy;
        float x1 = cx - 0.5f*wx, y1 = cy - 0.5f*wy;
        float x2 = x1 + wx,      y2 = y1 + wy;
        float W = vsz[img*2+0], H = vsz[img*2+1];
        x1 = fminf(fmaxf(x1,0.f),W); x2 = fminf(fmaxf(x2,0.f),W);
        y1 = fminf(fmaxf(y1,0.f),H); y2 = fminf(fmaxf(y2,0.f),H);
        box = make_float4(x1,y1,x2,y2);
        valid = (x2 - x1 > 0.001f) && (y2 - y1 > 0.001f);
        score = obj[(size_t)img*A_TOTAL + a];
    }
    g_boxes [task*NPAD + r] = box;
    g_scores[task*NPAD + r] = score;
    g_keys  [task*NPAD + r] = key;
    unsigned vm = __ballot_sync(0xffffffffu, valid);
    if ((tid & 31) == 0) g_validMask[task*NW + (tid>>5)] = vm;
}

// ---------------- K5: suppression bit-matrix, lower triangle, 32 rows/block ----------------
__global__ void __launch_bounds__(1024) k_supmat(){
    int task = blockIdx.y, bx = blockIdx.x;       // bx in [0,32): rows bx*32..bx*32+31
    __shared__ float4 sbox[NPAD];   // 16 KB
    __shared__ float  sar [NPAD];   //  4 KB
    int tid = threadIdx.x;
    int nwords = bx + 1;                          // all rows in block share (row>>5)==bx
    int lim = nwords * 32;
    for (int j=tid; j<lim; j+=1024){
        float4 bb = g_boxes[task*NPAD + j];
        sbox[j] = bb;
        sar[j]  = (bb.z - bb.x) * (bb.w - bb.y);
    }
    __syncthreads();
    int wid = tid >> 5, lane = tid & 31;
    int i = bx*32 + wid;           // row
    float4 bi = sbox[i];
    float tden = sar[i] + 1e-9f;
    unsigned* dst = &g_sup[((size_t)task*NPAD + i)*NW];
    for (int jw=0; jw<nwords; jw++){
        int j = jw*32 + lane;
        float4 bj = sbox[j];
        float xx1 = fmaxf(bi.x, bj.x);
        float yy1 = fmaxf(bi.y, bj.y);
        float xx2 = fminf(bi.z, bj.z);
        float yy2 = fminf(bi.w, bj.w);
        float iw = fmaxf(xx2-xx1, 0.f);
        float ih = fmaxf(yy2-yy1, 0.f);
        float inter = iw*ih;
        float den = tden + sar[j] - inter;
        bool sup = inter > 0.7f*den;        // == (iou > 0.7)
        unsigned m = __ballot_sync(0xffffffffu, sup);
        if (lane == 0) dst[jw] = m;
    }
}

// ---------------- K6: fixed-point NMS + fallback + (last task per image) merge/output ----------------
__global__ void __launch_bounds__(1024) k_nms_out(float* __restrict__ out){
    int task = blockIdx.x;
    int img = task / NLEV;
    int tid = threadIdx.x;
    int myw = tid >> 5, lane = tid & 31;
    unsigned row[NW];
    const uint4* rp = (const uint4*)(g_sup + ((size_t)task*NPAD + tid)*NW);
    #pragma unroll
    for (int q=0;q<8;q++){
        uint4 v = rp[q];
        row[q*4+0]=v.x; row[q*4+1]=v.y; row[q*4+2]=v.z; row[q*4+3]=v.w;
    }
    #pragma unroll
    for (int w=0;w<NW;w++) if (w > myw) row[w] = 0u;
    row[myw] &= (lane ? ((1u<<lane)-1u) : 0u);
    bool valid = (g_validMask[task*NW + myw] >> lane) & 1u;

    __shared__ unsigned skeep[NW];
    __shared__ int schanged, sconv;
    if (tid < NW) skeep[tid] = g_validMask[task*NW + tid];
    if (tid == 0) sconv = 0;
    __syncthreads();

    for (int it=0; it<24; ++it){
        unsigned any = 0u;
        #pragma unroll
        for (int w=0;w<NW;w++) any |= row[w] & skeep[w];
        bool nk = valid && (any == 0u);
        unsigned bw = __ballot_sync(0xffffffffu, nk);
        if (tid == 0) schanged = 0;
        __syncthreads();
        if (lane == 0){
            if (bw != skeep[myw]) schanged = 1;
            skeep[myw] = bw;
        }
        __syncthreads();
        if (!schanged){ if (tid==0) sconv = 1; break; }
    }
    __syncthreads();

    if (!sconv){
        // sequential greedy fallback (warp 0), lower-triangle-correct
        if (tid < 32){
            unsigned validw = g_validMask[task*NW + lane];
            const unsigned* rowbase = g_sup + (size_t)task*NPAD*NW;
            unsigned keptw = 0u;
            auto loadw = [&](int nx)->unsigned{
                if (nx >= NPAD) return 0u;
                int wi = nx >> 5;
                if (lane > wi) return 0u;
                unsigned r = rowbase[(size_t)nx*NW + lane];
                if (lane == wi) r &= ((nx & 31) ? ((1u<<(nx&31))-1u) : 0u);
                return r;
            };
            unsigned ring[8];
            #pragma unroll
            for (int d=0; d<8; d++) ring[d] = loadw(d);
            for (int ib=0; ib<NPAD; ib+=8){
                #pragma unroll
                for (int u=0; u<8; u++){
                    int i = ib + u;
                    int wi = i >> 5;
                    bool hit = (ring[u] & keptw) != 0u;
                    unsigned anyhit = __ballot_sync(0xffffffffu, hit);
                    unsigned vv = __shfl_sync(0xffffffffu, validw, wi);
                    bool take = ((vv >> (i & 31)) & 1u) && (anyhit == 0u);
                    if (take && lane == wi) keptw |= (1u << (i & 31));
                    ring[u] = loadw(i + 8);
                }
            }
            skeep[lane] = keptw;
        }
        __syncthreads();
    }

    // compaction (warp 0): kept list in score-descending order
    if (tid < 32){
        unsigned keepw = skeep[lane];
        unsigned cnt = __popc(keepw);
        unsigned incl = cnt;
        #pragma unroll
        for (int d=1; d<32; d<<=1){
            unsigned v = __shfl_up_sync(0xffffffffu, incl, d);
            if (lane >= d) incl += v;
        }
        unsigned excl = incl - cnt;
        unsigned total = __shfl_sync(0xffffffffu, incl, 31);
        if (lane == 0) g_kcnt[task] = (int)total;
        unsigned m = keepw; int p = (int)excl;
        while (m){
            int b = __ffs((int)m) - 1; m &= m - 1;
            int r = lane*32 + b;
            g_kkey[task*NPAD + p] = g_keys[task*NPAD + r];
            g_kref[task*NPAD + p] = r;
            p++;
        }
    }
    __syncthreads();
    __shared__ int slastD;
    if (tid == 0){
        __threadfence();                                    // release my kkey/kref/kcnt
        slastD = (atomicAdd(&g_doneD[img], 1) == NLEV-1) ? 1 : 0;
    }
    __syncthreads();
    if (!slastD) return;
    if (tid == 0){ g_doneD[img] = 0; __threadfence(); }     // acquire peers' writes; reset for next replay
    __syncthreads();

    // ---- merge phase: 5-way co-ranking merge for this image ----
    __shared__ unsigned skey[NLEV*NPAD];  // 20 KB
    __shared__ int scnt[NLEV];
    if (tid < NLEV) scnt[tid] = g_kcnt[img*NLEV + tid];
    for (int lt=0; lt<NLEV; lt++)
        skey[lt*NPAD + tid] = g_kkey[(img*NLEV + lt)*NPAD + tid];
    for (int i=tid; i<POST_TOPN*4; i+=1024) out[img*POST_TOPN*4 + i] = 0.f;
    for (int i=tid; i<POST_TOPN;   i+=1024) out[BS*POST_TOPN*4 + img*POST_TOPN + i] = 0.f;
    __syncthreads();
    for (int e=tid; e<NLEV*NPAD; e+=1024){
        int lt = e >> 10, p = e & (NPAD-1);
        if (p < scnt[lt]){
            unsigned key = skey[lt*NPAD + p];
            int rank = p;
            #pragma unroll
            for (int o=0; o<NLEV; o++){
                if (o == lt) continue;
                int c = scnt[o];
                const unsigned* arr = skey + o*NPAD;
                int lo=0, hi=c;
                while (lo < hi){
                    int mid = (lo+hi) >> 1;
                    bool before = (o < lt) ? (arr[mid] >= key) : (arr[mid] > key);
                    if (before) lo = mid+1; else hi = mid;
                }
                rank += lo;
            }
            if (rank < POST_TOPN){
                int t2 = img*NLEV + lt;
                int r = g_kref[t2*NPAD + p];
                float4 bb = g_boxes[t2*NPAD + r];
                float sc  = g_scores[t2*NPAD + r];
                float* ob = out + (img*POST_TOPN + rank)*4;
                ob[0]=bb.x; ob[1]=bb.y; ob[2]=bb.z; ob[3]=bb.w;
                out[BS*POST_TOPN*4 + img*POST_TOPN + rank] = sc;
            }
        }
    }
}

// ---------------- launch ----------------
extern "C" void kernel_launch(void* const* d_in, const int* in_sizes, int n_in,
                              void* d_out, int out_size){
    const float* pred = (const float*)d_in[0];   // (2, A, 4)
    const float* obj  = (const float*)d_in[1];   // (2, A, 1)
    const float* anch = (const float*)d_in[2];   // (A, 4)
    const float* vsz  = (const float*)d_in[3];   // (2, 2)
    float* out = (float*)d_out;                  // [boxes(2,1000,4) | scores(2,1000)]

    const int NQ = (BS*A_TOTAL)/4;               // 79941 float4s
    k_hist   <<<(NQ + 255)/256, 256>>>(obj);
    k_scan   <<<NTASK, 1024>>>();
    k_compact<<<(NQ + 255)/256, 256>>>(obj);
    k_gather <<<NTASK, 1024>>>(pred, obj, anch, vsz);
    k_supmat <<<dim3(NPAD/32, NTASK), 1024>>>();
    k_nms_out<<<NTASK, 1024>>>(out);
}